// round 2
// baseline (speedup 1.0000x reference)
#include <cuda_runtime.h>
#include <cuda_bf16.h>
#include <math.h>

// Problem constants (match reference)
#define NN   50000
#define EE   800000
#define GG   512
#define INF  128
#define HIDF 128
#define NH   8
#define HD   16
#define OUTC 128

#define SCALE_S 4.0f
#define COS_M 0.8775825618903728f
#define SIN_M 0.4794255386042030f

// ---------------- scratch (device globals; no cudaMalloc allowed) ------------
__device__ float g_feat1[NN * HIDF];
__device__ float g_el1[NN * NH];
__device__ float g_er1[NN * NH];
__device__ float g_h1[NN * HIDF];
__device__ float g_feat2[NN * HIDF];
__device__ float g_el2[NN];
__device__ float g_er2[NN];

__device__ int g_deg[NN];
__device__ int g_cursor[NN];
__device__ int g_incl[NN];
__device__ int g_rowptr[NN + 1];
__device__ int g_bsum[64];
__device__ int g_bsumex[64];
__device__ int g_esrc[EE];          // CSR payload: source node id directly

__device__ float g_gsum[GG * HIDF];
__device__ int   g_gcnt[GG];

// ---------------- init: zero accumulators -----------------------------------
__global__ void k_init() {
    int i = blockIdx.x * blockDim.x + threadIdx.x;
    if (i < NN) { g_deg[i] = 0; g_cursor[i] = 0; }
    if (i < GG * HIDF) g_gsum[i] = 0.0f;
    if (i < GG) g_gcnt[i] = 0;
}

// ---------------- fp32 GEMM: C[M,128] = A[M,128] @ B[128,128] ----------------
// BM=64, BN=128, BK=16, 256 threads, each thread 8x4 outputs.
// MODE 1: fused layer-1 attn logits (8 heads x 16 dims) into epilogue.
// MODE 2: fused layer-2 attn logits (1 head x 128 dims) into epilogue.
template <int MODE>
__global__ void k_gemm(const float* __restrict__ A, const float* __restrict__ B,
                       float* __restrict__ C, int M,
                       const float* __restrict__ al, const float* __restrict__ ar,
                       float* __restrict__ elo, float* __restrict__ ero) {
    __shared__ __align__(16) float As[64][16];
    __shared__ __align__(16) float Bs[16][128];
    int tid = threadIdx.x;
    int tx = tid & 31;   // col group (4 cols)
    int ty = tid >> 5;   // row group (8 rows)
    int rowBase = blockIdx.x * 64;

    float acc[8][4];
#pragma unroll
    for (int i = 0; i < 8; i++)
#pragma unroll
        for (int j = 0; j < 4; j++) acc[i][j] = 0.0f;

    for (int k0 = 0; k0 < 128; k0 += 16) {
        // load A tile: 64x16 = 256 float4
        {
            int r = tid >> 2;
            int c4 = (tid & 3) * 4;
            int gr = rowBase + r;
            float4 v = make_float4(0.f, 0.f, 0.f, 0.f);
            if (gr < M) v = *(const float4*)&A[gr * 128 + k0 + c4];
            *(float4*)&As[r][c4] = v;
        }
        // load B tile: 16x128 = 512 float4, 2 per thread
        {
#pragma unroll
            for (int i = 0; i < 2; i++) {
                int idx = tid + i * 256;
                int r = idx >> 5;
                int c4 = (idx & 31) * 4;
                *(float4*)&Bs[r][c4] = *(const float4*)&B[(k0 + r) * 128 + c4];
            }
        }
        __syncthreads();
#pragma unroll
        for (int kk = 0; kk < 16; kk++) {
            float4 bv = *(float4*)&Bs[kk][tx * 4];
            float b[4] = {bv.x, bv.y, bv.z, bv.w};
#pragma unroll
            for (int i = 0; i < 8; i++) {
                float a = As[ty * 8 + i][kk];
#pragma unroll
                for (int j = 0; j < 4; j++) acc[i][j] = fmaf(a, b[j], acc[i][j]);
            }
        }
        __syncthreads();
    }

    // attn-vector slices for this thread's 4 columns
    float av[4], rv[4];
    if (MODE != 0) {
        float4 a4 = *(const float4*)&al[tx * 4];
        float4 r4 = *(const float4*)&ar[tx * 4];
        av[0] = a4.x; av[1] = a4.y; av[2] = a4.z; av[3] = a4.w;
        rv[0] = r4.x; rv[1] = r4.y; rv[2] = r4.z; rv[3] = r4.w;
    }

#pragma unroll
    for (int i = 0; i < 8; i++) {
        int r = rowBase + ty * 8 + i;
        if (r >= M) continue;
        float4 v = make_float4(acc[i][0], acc[i][1], acc[i][2], acc[i][3]);
        *(float4*)&C[r * 128 + tx * 4] = v;
        if (MODE == 1) {
            // per-head (head = tx>>2, 16 dims over 4 lanes) dot products
            float pl = acc[i][0] * av[0] + acc[i][1] * av[1] + acc[i][2] * av[2] + acc[i][3] * av[3];
            float pr = acc[i][0] * rv[0] + acc[i][1] * rv[1] + acc[i][2] * rv[2] + acc[i][3] * rv[3];
            pl += __shfl_xor_sync(0xffffffffu, pl, 1);
            pl += __shfl_xor_sync(0xffffffffu, pl, 2);
            pr += __shfl_xor_sync(0xffffffffu, pr, 1);
            pr += __shfl_xor_sync(0xffffffffu, pr, 2);
            if ((tx & 3) == 0) {
                int head = tx >> 2;
                elo[r * 8 + head] = pl;
                ero[r * 8 + head] = pr;
            }
        } else if (MODE == 2) {
            float pl = acc[i][0] * av[0] + acc[i][1] * av[1] + acc[i][2] * av[2] + acc[i][3] * av[3];
            float pr = acc[i][0] * rv[0] + acc[i][1] * rv[1] + acc[i][2] * rv[2] + acc[i][3] * rv[3];
#pragma unroll
            for (int off = 16; off; off >>= 1) {
                pl += __shfl_xor_sync(0xffffffffu, pl, off);
                pr += __shfl_xor_sync(0xffffffffu, pr, off);
            }
            if (tx == 0) { elo[r] = pl; ero[r] = pr; }
        }
    }
}

// ---------------- CSR build --------------------------------------------------
__global__ void k_hist(const int* __restrict__ dst) {
    int i = blockIdx.x * blockDim.x + threadIdx.x;
    if (i < EE) atomicAdd(&g_deg[dst[i]], 1);
}

__global__ void k_scanA() {  // 1024 threads/block
    __shared__ int s[1024];
    int i = blockIdx.x * 1024 + threadIdx.x;
    int v = (i < NN) ? g_deg[i] : 0;
    s[threadIdx.x] = v;
    __syncthreads();
    for (int off = 1; off < 1024; off <<= 1) {
        int t = (threadIdx.x >= off) ? s[threadIdx.x - off] : 0;
        __syncthreads();
        s[threadIdx.x] += t;
        __syncthreads();
    }
    if (i < NN) g_incl[i] = s[threadIdx.x];
    if (threadIdx.x == 1023) g_bsum[blockIdx.x] = s[1023];
}

__global__ void k_scanB(int nblk) {
    if (threadIdx.x == 0) {
        int run = 0;
        for (int b = 0; b < nblk; b++) {
            int t = g_bsum[b];
            g_bsumex[b] = run;
            run += t;
        }
    }
}

__global__ void k_scanC() {
    int i = blockIdx.x * blockDim.x + threadIdx.x;
    if (i < NN) g_rowptr[i] = g_incl[i] - g_deg[i] + g_bsumex[i >> 10];
    if (i == NN) g_rowptr[NN] = EE;
}

__global__ void k_scatter(const int* __restrict__ dst, const int* __restrict__ src) {
    int i = blockIdx.x * blockDim.x + threadIdx.x;
    if (i < EE) {
        int d = dst[i];
        int pos = g_rowptr[d] + atomicAdd(&g_cursor[d], 1);
        g_esrc[pos] = src[i];
    }
}

// ---------------- GAT layer 1 aggregation (warp per dst node) ---------------
// out = elu( sum_e softmax(leaky(el[src]+er[dst])) * feat1[src] + b1 )
__global__ void k_agg1(const float* __restrict__ b1) {
    int n = (blockIdx.x * blockDim.x + threadIdx.x) >> 5;
    int lane = threadIdx.x & 31;
    if (n >= NN) return;
    int head = lane >> 2;
    float er_h = g_er1[n * 8 + head];
    int beg = g_rowptr[n], end = g_rowptr[n + 1];
    const float4* fv = (const float4*)g_feat1;
    float4 acc = make_float4(0.f, 0.f, 0.f, 0.f);
    float den = 0.0f;
    int i = beg;
    for (; i + 1 < end; i += 2) {
        int s0 = __ldg(&g_esrc[i]);
        int s1 = __ldg(&g_esrc[i + 1]);
        float x0 = __ldg(&g_el1[s0 * 8 + head]) + er_h;
        float x1 = __ldg(&g_el1[s1 * 8 + head]) + er_h;
        float4 f0 = fv[s0 * 32 + lane];
        float4 f1 = fv[s1 * 32 + lane];
        float w0 = __expf(x0 > 0.0f ? x0 : 0.2f * x0);
        float w1 = __expf(x1 > 0.0f ? x1 : 0.2f * x1);
        acc.x = fmaf(w0, f0.x, acc.x); acc.y = fmaf(w0, f0.y, acc.y);
        acc.z = fmaf(w0, f0.z, acc.z); acc.w = fmaf(w0, f0.w, acc.w);
        acc.x = fmaf(w1, f1.x, acc.x); acc.y = fmaf(w1, f1.y, acc.y);
        acc.z = fmaf(w1, f1.z, acc.z); acc.w = fmaf(w1, f1.w, acc.w);
        den += w0 + w1;
    }
    if (i < end) {
        int s0 = __ldg(&g_esrc[i]);
        float x0 = __ldg(&g_el1[s0 * 8 + head]) + er_h;
        float4 f0 = fv[s0 * 32 + lane];
        float w0 = __expf(x0 > 0.0f ? x0 : 0.2f * x0);
        acc.x = fmaf(w0, f0.x, acc.x); acc.y = fmaf(w0, f0.y, acc.y);
        acc.z = fmaf(w0, f0.z, acc.z); acc.w = fmaf(w0, f0.w, acc.w);
        den += w0;
    }
    float inv = den > 0.0f ? 1.0f / den : 0.0f;
    float4 bv = ((const float4*)b1)[lane];
    float4 v;
    v.x = acc.x * inv + bv.x;
    v.y = acc.y * inv + bv.y;
    v.z = acc.z * inv + bv.z;
    v.w = acc.w * inv + bv.w;
    // ELU
    v.x = v.x > 0.0f ? v.x : expm1f(v.x);
    v.y = v.y > 0.0f ? v.y : expm1f(v.y);
    v.z = v.z > 0.0f ? v.z : expm1f(v.z);
    v.w = v.w > 0.0f ? v.w : expm1f(v.w);
    ((float4*)g_h1)[n * 32 + lane] = v;
}

// ---------------- GAT layer 2 aggregation + residual + graph pooling --------
__global__ void k_agg2(const float* __restrict__ b2, const int* __restrict__ graph_ids) {
    int n = (blockIdx.x * blockDim.x + threadIdx.x) >> 5;
    int lane = threadIdx.x & 31;
    if (n >= NN) return;
    float er_n = g_er2[n];
    int beg = g_rowptr[n], end = g_rowptr[n + 1];
    const float4* fv = (const float4*)g_feat2;
    float4 acc = make_float4(0.f, 0.f, 0.f, 0.f);
    float den = 0.0f;
    int i = beg;
    for (; i + 1 < end; i += 2) {
        int s0 = __ldg(&g_esrc[i]);
        int s1 = __ldg(&g_esrc[i + 1]);
        float x0 = __ldg(&g_el2[s0]) + er_n;
        float x1 = __ldg(&g_el2[s1]) + er_n;
        float4 f0 = fv[s0 * 32 + lane];
        float4 f1 = fv[s1 * 32 + lane];
        float w0 = __expf(x0 > 0.0f ? x0 : 0.2f * x0);
        float w1 = __expf(x1 > 0.0f ? x1 : 0.2f * x1);
        acc.x = fmaf(w0, f0.x, acc.x); acc.y = fmaf(w0, f0.y, acc.y);
        acc.z = fmaf(w0, f0.z, acc.z); acc.w = fmaf(w0, f0.w, acc.w);
        acc.x = fmaf(w1, f1.x, acc.x); acc.y = fmaf(w1, f1.y, acc.y);
        acc.z = fmaf(w1, f1.z, acc.z); acc.w = fmaf(w1, f1.w, acc.w);
        den += w0 + w1;
    }
    if (i < end) {
        int s0 = __ldg(&g_esrc[i]);
        float x0 = __ldg(&g_el2[s0]) + er_n;
        float4 f0 = fv[s0 * 32 + lane];
        float w0 = __expf(x0 > 0.0f ? x0 : 0.2f * x0);
        acc.x = fmaf(w0, f0.x, acc.x); acc.y = fmaf(w0, f0.y, acc.y);
        acc.z = fmaf(w0, f0.z, acc.z); acc.w = fmaf(w0, f0.w, acc.w);
        den += w0;
    }
    float inv = den > 0.0f ? 1.0f / den : 0.0f;
    float4 res = ((const float4*)g_h1)[n * 32 + lane];
    float4 bv = ((const float4*)b2)[lane];
    float4 v;
    v.x = acc.x * inv + res.x + bv.x;
    v.y = acc.y * inv + res.y + bv.y;
    v.z = acc.z * inv + res.z + bv.z;
    v.w = acc.w * inv + res.w + bv.w;
    int g = __ldg(&graph_ids[n]);
    float* gs = &g_gsum[g * 128 + lane * 4];
    atomicAdd(&gs[0], v.x);
    atomicAdd(&gs[1], v.y);
    atomicAdd(&gs[2], v.z);
    atomicAdd(&gs[3], v.w);
    if (lane == 0) atomicAdd(&g_gcnt[g], 1);
}

// ---------------- ArcFace head ----------------------------------------------
// block per graph, 128 threads (one per output class)
__global__ void k_arcface(const float* __restrict__ Wa, const int* __restrict__ labels,
                          float* __restrict__ out) {
    __shared__ float emb[128];
    __shared__ float red[128];
    int g = blockIdx.x;
    int t = threadIdx.x;
    float cnt = (float)g_gcnt[g];
    float ic = 1.0f / fmaxf(cnt, 1.0f);
    float e = g_gsum[g * 128 + t] * ic;
    emb[t] = e;
    red[t] = e * e;
    __syncthreads();
    for (int s = 64; s > 0; s >>= 1) {
        if (t < s) red[t] += red[t + s];
        __syncthreads();
    }
    float invn = rsqrtf(red[0]);
    const float* wrow = Wa + t * 128;
    float dot = 0.0f, w2 = 0.0f;
#pragma unroll 4
    for (int k = 0; k < 128; k += 4) {
        float4 wv = *(const float4*)&wrow[k];
        dot += emb[k] * wv.x + emb[k + 1] * wv.y + emb[k + 2] * wv.z + emb[k + 3] * wv.w;
        w2 += wv.x * wv.x + wv.y * wv.y + wv.z * wv.z + wv.w * wv.w;
    }
    float c = dot * rsqrtf(w2) * invn;
    if (t == __ldg(&labels[g])) {
        float s2 = fmaxf(0.0f, 1.0f - c * c);
        c = c * COS_M - sqrtf(s2) * SIN_M;
    }
    out[g * 128 + t] = SCALE_S * c;
}

// ---------------- launcher ---------------------------------------------------
extern "C" void kernel_launch(void* const* d_in, const int* in_sizes, int n_in,
                              void* d_out, int out_size) {
    const float* x   = (const float*)d_in[0];
    const int* src   = (const int*)d_in[1];
    const int* dst   = (const int*)d_in[2];
    const int* gids  = (const int*)d_in[3];
    const int* labels= (const int*)d_in[4];
    const float* W1  = (const float*)d_in[5];
    const float* al1 = (const float*)d_in[6];
    const float* ar1 = (const float*)d_in[7];
    const float* b1  = (const float*)d_in[8];
    const float* W2  = (const float*)d_in[9];
    const float* al2 = (const float*)d_in[10];
    const float* ar2 = (const float*)d_in[11];
    const float* b2  = (const float*)d_in[12];
    const float* Wa  = (const float*)d_in[13];
    float* out = (float*)d_out;

    float *feat1, *feat2, *h1, *el1, *er1, *el2, *er2;
    cudaGetSymbolAddress((void**)&feat1, g_feat1);
    cudaGetSymbolAddress((void**)&feat2, g_feat2);
    cudaGetSymbolAddress((void**)&h1, g_h1);
    cudaGetSymbolAddress((void**)&el1, g_el1);
    cudaGetSymbolAddress((void**)&er1, g_er1);
    cudaGetSymbolAddress((void**)&el2, g_el2);
    cudaGetSymbolAddress((void**)&er2, g_er2);

    const int TB = 256;
    int nWarpBlocks = (NN * 32 + TB - 1) / TB;   // warp-per-node kernels
    int nEdgeBlocks = (EE + TB - 1) / TB;
    int nScanBlocks = (NN + 1023) / 1024;

    k_init<<<(GG * HIDF + TB - 1) / TB, TB>>>();

    // CSR build (independent of features)
    k_hist<<<nEdgeBlocks, TB>>>(dst);
    k_scanA<<<nScanBlocks, 1024>>>();
    k_scanB<<<1, 32>>>(nScanBlocks);
    k_scanC<<<(NN + 1 + TB - 1) / TB, TB>>>();
    k_scatter<<<nEdgeBlocks, TB>>>(dst, src);

    // layer 1 (GEMM with fused attn-logit epilogue)
    k_gemm<1><<<(NN + 63) / 64, 256>>>(x, W1, feat1, NN, al1, ar1, el1, er1);
    k_agg1<<<nWarpBlocks, TB>>>(b1);

    // layer 2
    k_gemm<2><<<(NN + 63) / 64, 256>>>(h1, W2, feat2, NN, al2, ar2, el2, er2);
    k_agg2<<<nWarpBlocks, TB>>>(b2, gids);

    // ArcFace head
    k_arcface<<<GG, 128>>>(Wa, labels, out);
}

// round 3
// speedup vs baseline: 1.2689x; 1.2689x over previous
#include <cuda_runtime.h>
#include <cuda_bf16.h>
#include <math.h>

// Problem constants (match reference)
#define NN   50000
#define EE   800000
#define GG   512
#define INF  128
#define HIDF 128
#define NH   8
#define HD   16
#define OUTC 128

#define SCALE_S 4.0f
#define COS_M 0.8775825618903728f
#define SIN_M 0.4794255386042030f

// ---------------- scratch (device globals; no cudaMalloc allowed) ------------
__device__ float g_feat1[NN * HIDF];
__device__ float g_el1[NN * NH];
__device__ float g_er1[NN * NH];
__device__ float g_h1[NN * HIDF];
__device__ float g_feat2[NN * HIDF];
__device__ float g_el2[NN];
__device__ float g_er2[NN];

__device__ int g_deg[NN];
__device__ int g_cursor[NN];
__device__ int g_incl[NN];
__device__ int g_rowptr[NN + 1];
__device__ int g_bsum[64];
__device__ int g_bsumex[64];
__device__ int g_esrc[EE];          // CSR payload: source node id directly

__device__ float g_gsum[GG * HIDF];
__device__ int   g_gcnt[GG];

// ---------------- init: zero accumulators -----------------------------------
__global__ void k_init() {
    int i = blockIdx.x * blockDim.x + threadIdx.x;
    if (i < NN) { g_deg[i] = 0; g_cursor[i] = 0; }
    if (i < GG * HIDF) g_gsum[i] = 0.0f;
    if (i < GG) g_gcnt[i] = 0;
}

// ---------------- TF32 tensor-core GEMM -------------------------------------
// C[M,128] = A[M,128] @ B[128,128], block tile 128x128, 8 warps x 16 rows,
// BK=32, mma.sync.m16n8k8.tf32. Fused attn-logit epilogue:
// MODE 1: 8 heads x 16 dims; MODE 2: 1 head x 128 dims.

__device__ __forceinline__ unsigned f2tf32(float f) {
    unsigned u;
    asm("cvt.rna.tf32.f32 %0, %1;" : "=r"(u) : "f"(f));
    return u;
}

__device__ __forceinline__ void mma_tf32(float* c, unsigned a0, unsigned a1,
                                         unsigned a2, unsigned a3,
                                         unsigned b0, unsigned b1) {
    asm volatile(
        "mma.sync.aligned.m16n8k8.row.col.f32.tf32.tf32.f32 "
        "{%0,%1,%2,%3}, {%4,%5,%6,%7}, {%8,%9}, {%0,%1,%2,%3};"
        : "+f"(c[0]), "+f"(c[1]), "+f"(c[2]), "+f"(c[3])
        : "r"(a0), "r"(a1), "r"(a2), "r"(a3), "r"(b0), "r"(b1));
}

#define AS_STRIDE 36
#define BS_STRIDE 136

template <int MODE>
__global__ void __launch_bounds__(256, 2)
k_gemm(const float* __restrict__ A, const float* __restrict__ B,
       float* __restrict__ C, int M,
       const float* __restrict__ al, const float* __restrict__ ar,
       float* __restrict__ elo, float* __restrict__ ero) {
    __shared__ __align__(16) unsigned As[128 * AS_STRIDE];
    __shared__ __align__(16) unsigned Bs[32 * BS_STRIDE];

    int tid = threadIdx.x;
    int w = tid >> 5;           // warp 0..7
    int lane = tid & 31;
    int q = lane >> 2;          // 0..7
    int s = lane & 3;           // 0..3
    int rowBase = blockIdx.x * 128;
    int warpRow = w * 16;

    float acc[16][4];
#pragma unroll
    for (int nt = 0; nt < 16; nt++)
#pragma unroll
        for (int j = 0; j < 4; j++) acc[nt][j] = 0.0f;

    for (int k0 = 0; k0 < 128; k0 += 32) {
        // load A tile: 128 rows x 32 cols (tf32-round at store)
#pragma unroll
        for (int it = 0; it < 4; it++) {
            int idx = tid + it * 256;
            int r = idx >> 3;
            int c4 = (idx & 7) * 4;
            int gr = rowBase + r;
            float4 v = make_float4(0.f, 0.f, 0.f, 0.f);
            if (gr < M) v = *(const float4*)&A[gr * 128 + k0 + c4];
            unsigned* p = &As[r * AS_STRIDE + c4];
            p[0] = f2tf32(v.x); p[1] = f2tf32(v.y);
            p[2] = f2tf32(v.z); p[3] = f2tf32(v.w);
        }
        // load B tile: 32 rows x 128 cols
#pragma unroll
        for (int it = 0; it < 4; it++) {
            int idx = tid + it * 256;
            int r = idx >> 5;
            int c4 = (idx & 31) * 4;
            float4 v = *(const float4*)&B[(k0 + r) * 128 + c4];
            unsigned* p = &Bs[r * BS_STRIDE + c4];
            p[0] = f2tf32(v.x); p[1] = f2tf32(v.y);
            p[2] = f2tf32(v.z); p[3] = f2tf32(v.w);
        }
        __syncthreads();

#pragma unroll
        for (int kk = 0; kk < 32; kk += 8) {
            unsigned a0 = As[(warpRow + q) * AS_STRIDE + kk + s];
            unsigned a1 = As[(warpRow + q + 8) * AS_STRIDE + kk + s];
            unsigned a2 = As[(warpRow + q) * AS_STRIDE + kk + s + 4];
            unsigned a3 = As[(warpRow + q + 8) * AS_STRIDE + kk + s + 4];
#pragma unroll
            for (int nt = 0; nt < 16; nt++) {
                unsigned b0 = Bs[(kk + s) * BS_STRIDE + nt * 8 + q];
                unsigned b1 = Bs[(kk + s + 4) * BS_STRIDE + nt * 8 + q];
                mma_tf32(acc[nt], a0, a1, a2, a3, b0, b1);
            }
        }
        __syncthreads();
    }

    // rows owned by this thread
    int rA = rowBase + warpRow + q;
    int rB = rA + 8;

    // preload attn vector pairs for this thread's columns
    float2 alv[16], arv[16];
#pragma unroll
    for (int nt = 0; nt < 16; nt++) {
        int col = nt * 8 + 2 * s;
        alv[nt] = *(const float2*)&al[col];
        arv[nt] = *(const float2*)&ar[col];
    }

    // store C
    if (rA < M) {
#pragma unroll
        for (int nt = 0; nt < 16; nt++) {
            int col = nt * 8 + 2 * s;
            *(float2*)&C[rA * 128 + col] = make_float2(acc[nt][0], acc[nt][1]);
        }
    }
    if (rB < M) {
#pragma unroll
        for (int nt = 0; nt < 16; nt++) {
            int col = nt * 8 + 2 * s;
            *(float2*)&C[rB * 128 + col] = make_float2(acc[nt][2], acc[nt][3]);
        }
    }

    if (MODE == 1) {
        // 8 heads, head h covers nt in {2h, 2h+1}
#pragma unroll
        for (int h = 0; h < 8; h++) {
            float plA = 0.f, prA = 0.f, plB = 0.f, prB = 0.f;
#pragma unroll
            for (int k = 2 * h; k <= 2 * h + 1; k++) {
                plA += acc[k][0] * alv[k].x + acc[k][1] * alv[k].y;
                prA += acc[k][0] * arv[k].x + acc[k][1] * arv[k].y;
                plB += acc[k][2] * alv[k].x + acc[k][3] * alv[k].y;
                prB += acc[k][2] * arv[k].x + acc[k][3] * arv[k].y;
            }
            plA += __shfl_xor_sync(0xffffffffu, plA, 1);
            plA += __shfl_xor_sync(0xffffffffu, plA, 2);
            prA += __shfl_xor_sync(0xffffffffu, prA, 1);
            prA += __shfl_xor_sync(0xffffffffu, prA, 2);
            plB += __shfl_xor_sync(0xffffffffu, plB, 1);
            plB += __shfl_xor_sync(0xffffffffu, plB, 2);
            prB += __shfl_xor_sync(0xffffffffu, prB, 1);
            prB += __shfl_xor_sync(0xffffffffu, prB, 2);
            if (s == 0) {
                if (rA < M) { elo[rA * 8 + h] = plA; ero[rA * 8 + h] = prA; }
                if (rB < M) { elo[rB * 8 + h] = plB; ero[rB * 8 + h] = prB; }
            }
        }
    } else {
        // single head over all 128 cols
        float plA = 0.f, prA = 0.f, plB = 0.f, prB = 0.f;
#pragma unroll
        for (int nt = 0; nt < 16; nt++) {
            plA += acc[nt][0] * alv[nt].x + acc[nt][1] * alv[nt].y;
            prA += acc[nt][0] * arv[nt].x + acc[nt][1] * arv[nt].y;
            plB += acc[nt][2] * alv[nt].x + acc[nt][3] * alv[nt].y;
            prB += acc[nt][2] * arv[nt].x + acc[nt][3] * arv[nt].y;
        }
        plA += __shfl_xor_sync(0xffffffffu, plA, 1);
        plA += __shfl_xor_sync(0xffffffffu, plA, 2);
        prA += __shfl_xor_sync(0xffffffffu, prA, 1);
        prA += __shfl_xor_sync(0xffffffffu, prA, 2);
        plB += __shfl_xor_sync(0xffffffffu, plB, 1);
        plB += __shfl_xor_sync(0xffffffffu, plB, 2);
        prB += __shfl_xor_sync(0xffffffffu, prB, 1);
        prB += __shfl_xor_sync(0xffffffffu, prB, 2);
        if (s == 0) {
            if (rA < M) { elo[rA] = plA; ero[rA] = prA; }
            if (rB < M) { elo[rB] = plB; ero[rB] = prB; }
        }
    }
}

// ---------------- CSR build --------------------------------------------------
__global__ void k_hist(const int* __restrict__ dst) {
    int i = blockIdx.x * blockDim.x + threadIdx.x;
    if (i < EE) atomicAdd(&g_deg[dst[i]], 1);
}

__global__ void k_scanA() {  // 1024 threads/block
    __shared__ int s[1024];
    int i = blockIdx.x * 1024 + threadIdx.x;
    int v = (i < NN) ? g_deg[i] : 0;
    s[threadIdx.x] = v;
    __syncthreads();
    for (int off = 1; off < 1024; off <<= 1) {
        int t = (threadIdx.x >= off) ? s[threadIdx.x - off] : 0;
        __syncthreads();
        s[threadIdx.x] += t;
        __syncthreads();
    }
    if (i < NN) g_incl[i] = s[threadIdx.x];
    if (threadIdx.x == 1023) g_bsum[blockIdx.x] = s[1023];
}

__global__ void k_scanB(int nblk) {  // 64-thread parallel scan
    __shared__ int s[64];
    int t = threadIdx.x;
    int v = (t < nblk) ? g_bsum[t] : 0;
    s[t] = v;
    __syncthreads();
    for (int off = 1; off < 64; off <<= 1) {
        int u = (t >= off) ? s[t - off] : 0;
        __syncthreads();
        s[t] += u;
        __syncthreads();
    }
    if (t < nblk) g_bsumex[t] = s[t] - v;
}

__global__ void k_scanC() {
    int i = blockIdx.x * blockDim.x + threadIdx.x;
    if (i < NN) g_rowptr[i] = g_incl[i] - g_deg[i] + g_bsumex[i >> 10];
    if (i == NN) g_rowptr[NN] = EE;
}

__global__ void k_scatter(const int* __restrict__ dst, const int* __restrict__ src) {
    int i = blockIdx.x * blockDim.x + threadIdx.x;
    if (i < EE) {
        int d = dst[i];
        int pos = g_rowptr[d] + atomicAdd(&g_cursor[d], 1);
        g_esrc[pos] = src[i];
    }
}

// ---------------- GAT layer 1 aggregation (warp per dst node) ---------------
__global__ void k_agg1(const float* __restrict__ b1) {
    int n = (blockIdx.x * blockDim.x + threadIdx.x) >> 5;
    int lane = threadIdx.x & 31;
    if (n >= NN) return;
    int head = lane >> 2;
    float er_h = g_er1[n * 8 + head];
    int beg = g_rowptr[n], end = g_rowptr[n + 1];
    const float4* fv = (const float4*)g_feat1;
    float4 acc = make_float4(0.f, 0.f, 0.f, 0.f);
    float den = 0.0f;
    int i = beg;
    for (; i + 1 < end; i += 2) {
        int s0 = __ldg(&g_esrc[i]);
        int s1 = __ldg(&g_esrc[i + 1]);
        float x0 = __ldg(&g_el1[s0 * 8 + head]) + er_h;
        float x1 = __ldg(&g_el1[s1 * 8 + head]) + er_h;
        float4 f0 = fv[s0 * 32 + lane];
        float4 f1 = fv[s1 * 32 + lane];
        float w0 = __expf(x0 > 0.0f ? x0 : 0.2f * x0);
        float w1 = __expf(x1 > 0.0f ? x1 : 0.2f * x1);
        acc.x = fmaf(w0, f0.x, acc.x); acc.y = fmaf(w0, f0.y, acc.y);
        acc.z = fmaf(w0, f0.z, acc.z); acc.w = fmaf(w0, f0.w, acc.w);
        acc.x = fmaf(w1, f1.x, acc.x); acc.y = fmaf(w1, f1.y, acc.y);
        acc.z = fmaf(w1, f1.z, acc.z); acc.w = fmaf(w1, f1.w, acc.w);
        den += w0 + w1;
    }
    if (i < end) {
        int s0 = __ldg(&g_esrc[i]);
        float x0 = __ldg(&g_el1[s0 * 8 + head]) + er_h;
        float4 f0 = fv[s0 * 32 + lane];
        float w0 = __expf(x0 > 0.0f ? x0 : 0.2f * x0);
        acc.x = fmaf(w0, f0.x, acc.x); acc.y = fmaf(w0, f0.y, acc.y);
        acc.z = fmaf(w0, f0.z, acc.z); acc.w = fmaf(w0, f0.w, acc.w);
        den += w0;
    }
    float inv = den > 0.0f ? 1.0f / den : 0.0f;
    float4 bv = ((const float4*)b1)[lane];
    float4 v;
    v.x = acc.x * inv + bv.x;
    v.y = acc.y * inv + bv.y;
    v.z = acc.z * inv + bv.z;
    v.w = acc.w * inv + bv.w;
    v.x = v.x > 0.0f ? v.x : expm1f(v.x);
    v.y = v.y > 0.0f ? v.y : expm1f(v.y);
    v.z = v.z > 0.0f ? v.z : expm1f(v.z);
    v.w = v.w > 0.0f ? v.w : expm1f(v.w);
    ((float4*)g_h1)[n * 32 + lane] = v;
}

// ---------------- GAT layer 2 aggregation + residual + graph pooling --------
__global__ void k_agg2(const float* __restrict__ b2, const int* __restrict__ graph_ids) {
    int n = (blockIdx.x * blockDim.x + threadIdx.x) >> 5;
    int lane = threadIdx.x & 31;
    if (n >= NN) return;
    float er_n = g_er2[n];
    int beg = g_rowptr[n], end = g_rowptr[n + 1];
    const float4* fv = (const float4*)g_feat2;
    float4 acc = make_float4(0.f, 0.f, 0.f, 0.f);
    float den = 0.0f;
    int i = beg;
    for (; i + 1 < end; i += 2) {
        int s0 = __ldg(&g_esrc[i]);
        int s1 = __ldg(&g_esrc[i + 1]);
        float x0 = __ldg(&g_el2[s0]) + er_n;
        float x1 = __ldg(&g_el2[s1]) + er_n;
        float4 f0 = fv[s0 * 32 + lane];
        float4 f1 = fv[s1 * 32 + lane];
        float w0 = __expf(x0 > 0.0f ? x0 : 0.2f * x0);
        float w1 = __expf(x1 > 0.0f ? x1 : 0.2f * x1);
        acc.x = fmaf(w0, f0.x, acc.x); acc.y = fmaf(w0, f0.y, acc.y);
        acc.z = fmaf(w0, f0.z, acc.z); acc.w = fmaf(w0, f0.w, acc.w);
        acc.x = fmaf(w1, f1.x, acc.x); acc.y = fmaf(w1, f1.y, acc.y);
        acc.z = fmaf(w1, f1.z, acc.z); acc.w = fmaf(w1, f1.w, acc.w);
        den += w0 + w1;
    }
    if (i < end) {
        int s0 = __ldg(&g_esrc[i]);
        float x0 = __ldg(&g_el2[s0]) + er_n;
        float4 f0 = fv[s0 * 32 + lane];
        float w0 = __expf(x0 > 0.0f ? x0 : 0.2f * x0);
        acc.x = fmaf(w0, f0.x, acc.x); acc.y = fmaf(w0, f0.y, acc.y);
        acc.z = fmaf(w0, f0.z, acc.z); acc.w = fmaf(w0, f0.w, acc.w);
        den += w0;
    }
    float inv = den > 0.0f ? 1.0f / den : 0.0f;
    float4 res = ((const float4*)g_h1)[n * 32 + lane];
    float4 bv = ((const float4*)b2)[lane];
    float4 v;
    v.x = acc.x * inv + res.x + bv.x;
    v.y = acc.y * inv + res.y + bv.y;
    v.z = acc.z * inv + res.z + bv.z;
    v.w = acc.w * inv + res.w + bv.w;
    int g = __ldg(&graph_ids[n]);
    float* gs = &g_gsum[g * 128 + lane * 4];
    atomicAdd(&gs[0], v.x);
    atomicAdd(&gs[1], v.y);
    atomicAdd(&gs[2], v.z);
    atomicAdd(&gs[3], v.w);
    if (lane == 0) atomicAdd(&g_gcnt[g], 1);
}

// ---------------- ArcFace head ----------------------------------------------
__global__ void k_arcface(const float* __restrict__ Wa, const int* __restrict__ labels,
                          float* __restrict__ out) {
    __shared__ float emb[128];
    __shared__ float red[128];
    int g = blockIdx.x;
    int t = threadIdx.x;
    float cnt = (float)g_gcnt[g];
    float ic = 1.0f / fmaxf(cnt, 1.0f);
    float e = g_gsum[g * 128 + t] * ic;
    emb[t] = e;
    red[t] = e * e;
    __syncthreads();
    for (int s = 64; s > 0; s >>= 1) {
        if (t < s) red[t] += red[t + s];
        __syncthreads();
    }
    float invn = rsqrtf(red[0]);
    const float* wrow = Wa + t * 128;
    float dot = 0.0f, w2 = 0.0f;
#pragma unroll 4
    for (int k = 0; k < 128; k += 4) {
        float4 wv = *(const float4*)&wrow[k];
        dot += emb[k] * wv.x + emb[k + 1] * wv.y + emb[k + 2] * wv.z + emb[k + 3] * wv.w;
        w2 += wv.x * wv.x + wv.y * wv.y + wv.z * wv.z + wv.w * wv.w;
    }
    float c = dot * rsqrtf(w2) * invn;
    if (t == __ldg(&labels[g])) {
        float s2 = fmaxf(0.0f, 1.0f - c * c);
        c = c * COS_M - sqrtf(s2) * SIN_M;
    }
    out[g * 128 + t] = SCALE_S * c;
}

// ---------------- launcher ---------------------------------------------------
extern "C" void kernel_launch(void* const* d_in, const int* in_sizes, int n_in,
                              void* d_out, int out_size) {
    const float* x   = (const float*)d_in[0];
    const int* src   = (const int*)d_in[1];
    const int* dst   = (const int*)d_in[2];
    const int* gids  = (const int*)d_in[3];
    const int* labels= (const int*)d_in[4];
    const float* W1  = (const float*)d_in[5];
    const float* al1 = (const float*)d_in[6];
    const float* ar1 = (const float*)d_in[7];
    const float* b1  = (const float*)d_in[8];
    const float* W2  = (const float*)d_in[9];
    const float* al2 = (const float*)d_in[10];
    const float* ar2 = (const float*)d_in[11];
    const float* b2  = (const float*)d_in[12];
    const float* Wa  = (const float*)d_in[13];
    float* out = (float*)d_out;

    float *feat1, *feat2, *h1, *el1, *er1, *el2, *er2;
    cudaGetSymbolAddress((void**)&feat1, g_feat1);
    cudaGetSymbolAddress((void**)&feat2, g_feat2);
    cudaGetSymbolAddress((void**)&h1, g_h1);
    cudaGetSymbolAddress((void**)&el1, g_el1);
    cudaGetSymbolAddress((void**)&er1, g_er1);
    cudaGetSymbolAddress((void**)&el2, g_el2);
    cudaGetSymbolAddress((void**)&er2, g_er2);

    const int TB = 256;
    int nWarpBlocks = (NN * 32 + TB - 1) / TB;   // warp-per-node kernels
    int nEdgeBlocks = (EE + TB - 1) / TB;
    int nScanBlocks = (NN + 1023) / 1024;

    k_init<<<(GG * HIDF + TB - 1) / TB, TB>>>();

    // CSR build (independent of features)
    k_hist<<<nEdgeBlocks, TB>>>(dst);
    k_scanA<<<nScanBlocks, 1024>>>();
    k_scanB<<<1, 64>>>(nScanBlocks);
    k_scanC<<<(NN + 1 + TB - 1) / TB, TB>>>();
    k_scatter<<<nEdgeBlocks, TB>>>(dst, src);

    // layer 1 (tensor-core GEMM with fused attn-logit epilogue)
    k_gemm<1><<<(NN + 127) / 128, 256>>>(x, W1, feat1, NN, al1, ar1, el1, er1);
    k_agg1<<<nWarpBlocks, TB>>>(b1);

    // layer 2
    k_gemm<2><<<(NN + 127) / 128, 256>>>(h1, W2, feat2, NN, al2, ar2, el2, er2);
    k_agg2<<<nWarpBlocks, TB>>>(b2, gids);

    // ArcFace head
    k_arcface<<<GG, 128>>>(Wa, labels, out);
}